// round 4
// baseline (speedup 1.0000x reference)
#include <cuda_runtime.h>

#define NCLS 256

// Closed-form Cholesky factors of C0 = (K+0.001)*I - 11^T:
//   L0[j,j] = d_j, L0[i,j] = c_j (i > j)  [column-constant below diagonal]
//   u_j = g*(g-1-j)/(g-j), d_j = sqrt(u_j), c_j = -sqrt(g/((g-j)*(g-1-j)))
// with g = fp32-rounded (K + 0.001), matching the reference's fp32 C0.
__device__ float g_c[NCLS];
__device__ float g_d[NCLS];

__global__ void init_cd_kernel() {
    int j = threadIdx.x;
    if (j < NCLS) {
        double g = (double)(256.001f);      // fp32(K + 0.001), exact-matched to reference C0
        double a = g - (double)j;           // g - j
        double b = a - 1.0;                 // g - 1 - j
        g_d[j] = (float)sqrt(g * b / a);
        g_c[j] = (float)(-sqrt(g / (a * b)));
    }
}

// One warp per (b,s) row. Lane owns 8 contiguous classes.
__global__ __launch_bounds__(256) void dbf_kernel(
    const int* __restrict__ data, const float* __restrict__ t,
    const float* __restrict__ noise, float* __restrict__ out, int rows)
{
    int gw   = (int)((blockIdx.x * blockDim.x + threadIdx.x) >> 5);
    int lane = threadIdx.x & 31;
    if (gw >= rows) return;

    float tv = __ldg(t + gw);
    float sb = fminf(tv, 1.0f - 1e-6f);
    bool  lo = sb < 1e-10f;
    sb = fmaxf(sb, 1e-10f);
    float beta = sb * sb;
    int   x    = __ldg(data + gw);

    const float4* np = (const float4*)noise + (size_t)gw * (NCLS / 4) + lane * 2;
    float4 na = np[0];
    float4 nb = np[1];
    float4 ca = ((const float4*)g_c)[lane * 2];
    float4 cb = ((const float4*)g_c)[lane * 2 + 1];
    float4 da = ((const float4*)g_d)[lane * 2];
    float4 db = ((const float4*)g_d)[lane * 2 + 1];

    float n[8] = {na.x, na.y, na.z, na.w, nb.x, nb.y, nb.z, nb.w};
    float c[8] = {ca.x, ca.y, ca.z, ca.w, cb.x, cb.y, cb.z, cb.w};
    float d[8] = {da.x, da.y, da.z, da.w, db.x, db.y, db.z, db.w};

    // Thread-local exclusive scan of c_j * n_j
    float P[8];
    float acc = 0.0f;
#pragma unroll
    for (int i = 0; i < 8; i++) { P[i] = acc; acc = fmaf(c[i], n[i], acc); }

    // Warp exclusive scan of per-thread totals
    float sc = acc;
#pragma unroll
    for (int o = 1; o < 32; o <<= 1) {
        float v = __shfl_up_sync(0xffffffffu, sc, o);
        if (lane >= o) sc += v;
    }
    float excl = sc - acc;

    // logits_j = beta*(256*[j==x] - 1) + sqrt(beta) * (prefix_j + d_j*n_j)
    int jbase = lane * 8;
    float lg[8];
#pragma unroll
    for (int i = 0; i < 8; i++) {
        float y = (excl + P[i]) + d[i] * n[i];
        float m = (jbase + i == x) ? 256.0f * beta : 0.0f;
        lg[i] = (m - beta) + sb * y;
    }

    // Softmax over 256 (local + warp shuffle reductions)
    float mx = lg[0];
#pragma unroll
    for (int i = 1; i < 8; i++) mx = fmaxf(mx, lg[i]);
#pragma unroll
    for (int o = 16; o > 0; o >>= 1) mx = fmaxf(mx, __shfl_xor_sync(0xffffffffu, mx, o));

    float ssum = 0.0f;
#pragma unroll
    for (int i = 0; i < 8; i++) { lg[i] = __expf(lg[i] - mx); ssum += lg[i]; }
#pragma unroll
    for (int o = 16; o > 0; o >>= 1) ssum += __shfl_xor_sync(0xffffffffu, ssum, o);

    float inv = __fdividef(1.0f, ssum);
#pragma unroll
    for (int i = 0; i < 8; i++) lg[i] = lo ? (1.0f / 256.0f) : lg[i] * inv;

    float4* op = (float4*)out + (size_t)gw * (NCLS / 4) + lane * 2;
    op[0] = make_float4(lg[0], lg[1], lg[2], lg[3]);
    op[1] = make_float4(lg[4], lg[5], lg[6], lg[7]);
}

extern "C" void kernel_launch(void* const* d_in, const int* in_sizes, int n_in,
                              void* d_out, int out_size) {
    const int*   data  = (const int*)d_in[0];
    const float* t     = (const float*)d_in[1];
    const float* noise = (const float*)d_in[2];
    float*       out   = (float*)d_out;
    int rows = in_sizes[1];                 // B*S = 16384

    init_cd_kernel<<<1, NCLS>>>();
    int blocks = (rows + 7) / 8;            // 8 warps/block, 1 warp per row
    dbf_kernel<<<blocks, 256>>>(data, t, noise, out, rows);
}

// round 5
// speedup vs baseline: 1.4048x; 1.4048x over previous
#include <cuda_runtime.h>

#define NCLS 256

// ---------------------------------------------------------------------------
// Compile-time closed-form Cholesky factors of C0 = (K+0.001)*I - 11^T:
//   L0[j,j] = d_j, L0[i,j] = c_j (i > j)  [column-constant below diagonal]
//   u_j = g*(g-1-j)/(g-j), d_j = sqrt(u_j), c_j = -sqrt(g/((g-j)*(g-1-j)))
// with g = fp32-rounded (K + 0.001), matching the reference's fp32 C0.
// Generated at COMPILE TIME via constexpr Newton sqrt -> no init kernel.
// ---------------------------------------------------------------------------
struct Tbl { float c[NCLS]; float d[NCLS]; };

__host__ __device__ constexpr double csqrt_(double x) {
    double r = x > 1.0 ? x : 1.0;
    for (int i = 0; i < 50; ++i) r = 0.5 * (r + x / r);
    return r;
}

__host__ __device__ constexpr Tbl make_tbl_() {
    Tbl t{};
    const double g = (double)256.001f;   // fp32(K + 0.001), matches reference C0
    for (int j = 0; j < NCLS; ++j) {
        double a = g - (double)j;        // g - j
        double b = a - 1.0;              // g - 1 - j
        t.d[j] = (float)csqrt_(g * b / a);
        t.c[j] = (float)(-csqrt_(g / (a * b)));
    }
    return t;
}

__device__ const Tbl g_tbl = make_tbl_();

// ---------------------------------------------------------------------------
// One warp per TWO (b,s) rows (interleaved for ILP). Lane owns 8 contiguous
// classes of each row. Matvec with L0 collapses to a weighted prefix sum:
//   y_j = sum_{k<j} c_k*n_k + d_j*n_j
// ---------------------------------------------------------------------------
__global__ __launch_bounds__(256) void dbf_kernel(
    const int* __restrict__ data, const float* __restrict__ t,
    const float* __restrict__ noise, float* __restrict__ out, int rows)
{
    int warp = (int)((blockIdx.x * blockDim.x + threadIdx.x) >> 5);
    int lane = threadIdx.x & 31;
    int r0 = warp * 2;
    if (r0 >= rows) return;
    int r1 = (r0 + 1 < rows) ? (r0 + 1) : r0;   // rows is even in practice

    // Per-row scalars
    float tv[2]; tv[0] = __ldg(t + r0); tv[1] = __ldg(t + r1);
    int   xx[2]; xx[0] = __ldg(data + r0); xx[1] = __ldg(data + r1);
    float sb[2], beta[2]; bool lo[2];
#pragma unroll
    for (int r = 0; r < 2; r++) {
        float s = fminf(tv[r], 1.0f - 1e-6f);
        lo[r] = s < 1e-10f;
        s = fmaxf(s, 1e-10f);
        sb[r] = s;
        beta[r] = s * s;
    }

    // Table (c, d) for this lane's 8 classes (LDG, L1-cached, broadcast-free)
    float4 ca = ((const float4*)g_tbl.c)[lane * 2];
    float4 cb = ((const float4*)g_tbl.c)[lane * 2 + 1];
    float4 da = ((const float4*)g_tbl.d)[lane * 2];
    float4 db = ((const float4*)g_tbl.d)[lane * 2 + 1];
    float c[8] = {ca.x, ca.y, ca.z, ca.w, cb.x, cb.y, cb.z, cb.w};
    float d[8] = {da.x, da.y, da.z, da.w, db.x, db.y, db.z, db.w};

    // Noise for both rows (2x float4 each, back-to-back for MLP)
    const float4* np0 = (const float4*)noise + (size_t)r0 * (NCLS / 4) + lane * 2;
    const float4* np1 = (const float4*)noise + (size_t)r1 * (NCLS / 4) + lane * 2;
    float4 n0a = np0[0], n0b = np0[1];
    float4 n1a = np1[0], n1b = np1[1];
    float n[2][8] = {
        {n0a.x, n0a.y, n0a.z, n0a.w, n0b.x, n0b.y, n0b.z, n0b.w},
        {n1a.x, n1a.y, n1a.z, n1a.w, n1b.x, n1b.y, n1b.z, n1b.w}
    };

    // Thread-local exclusive scan of c_j * n_j (both rows, interleaved)
    float P[2][8];
    float acc[2] = {0.0f, 0.0f};
#pragma unroll
    for (int i = 0; i < 8; i++) {
#pragma unroll
        for (int r = 0; r < 2; r++) {
            P[r][i] = acc[r];
            acc[r] = fmaf(c[i], n[r][i], acc[r]);
        }
    }

    // Warp exclusive scan of per-thread totals — two chains interleaved so the
    // ~30-cycle SHFL latencies overlap.
    float sc0 = acc[0], sc1 = acc[1];
#pragma unroll
    for (int o = 1; o < 32; o <<= 1) {
        float v0 = __shfl_up_sync(0xffffffffu, sc0, o);
        float v1 = __shfl_up_sync(0xffffffffu, sc1, o);
        if (lane >= o) { sc0 += v0; sc1 += v1; }
    }
    float excl[2] = {sc0 - acc[0], sc1 - acc[1]};

    // logits_j = beta*(256*[j==x] - 1) + sqrt(beta) * (prefix_j + d_j*n_j)
    int jbase = lane * 8;
    float lg[2][8];
#pragma unroll
    for (int i = 0; i < 8; i++) {
#pragma unroll
        for (int r = 0; r < 2; r++) {
            float y = (excl[r] + P[r][i]) + d[i] * n[r][i];
            float m = (jbase + i == xx[r]) ? 256.0f * beta[r] : 0.0f;
            lg[r][i] = (m - beta[r]) + sb[r] * y;
        }
    }

    // Softmax over 256: local max -> warp max (interleaved trees)
    float mx0 = lg[0][0], mx1 = lg[1][0];
#pragma unroll
    for (int i = 1; i < 8; i++) { mx0 = fmaxf(mx0, lg[0][i]); mx1 = fmaxf(mx1, lg[1][i]); }
#pragma unroll
    for (int o = 16; o > 0; o >>= 1) {
        float v0 = __shfl_xor_sync(0xffffffffu, mx0, o);
        float v1 = __shfl_xor_sync(0xffffffffu, mx1, o);
        mx0 = fmaxf(mx0, v0); mx1 = fmaxf(mx1, v1);
    }

    float s0 = 0.0f, s1 = 0.0f;
#pragma unroll
    for (int i = 0; i < 8; i++) {
        lg[0][i] = __expf(lg[0][i] - mx0); s0 += lg[0][i];
        lg[1][i] = __expf(lg[1][i] - mx1); s1 += lg[1][i];
    }
#pragma unroll
    for (int o = 16; o > 0; o >>= 1) {
        s0 += __shfl_xor_sync(0xffffffffu, s0, o);
        s1 += __shfl_xor_sync(0xffffffffu, s1, o);
    }

    float inv0 = __fdividef(1.0f, s0);
    float inv1 = __fdividef(1.0f, s1);
#pragma unroll
    for (int i = 0; i < 8; i++) {
        lg[0][i] = lo[0] ? (1.0f / 256.0f) : lg[0][i] * inv0;
        lg[1][i] = lo[1] ? (1.0f / 256.0f) : lg[1][i] * inv1;
    }

    float4* op0 = (float4*)out + (size_t)r0 * (NCLS / 4) + lane * 2;
    float4* op1 = (float4*)out + (size_t)r1 * (NCLS / 4) + lane * 2;
    op0[0] = make_float4(lg[0][0], lg[0][1], lg[0][2], lg[0][3]);
    op0[1] = make_float4(lg[0][4], lg[0][5], lg[0][6], lg[0][7]);
    op1[0] = make_float4(lg[1][0], lg[1][1], lg[1][2], lg[1][3]);
    op1[1] = make_float4(lg[1][4], lg[1][5], lg[1][6], lg[1][7]);
}

extern "C" void kernel_launch(void* const* d_in, const int* in_sizes, int n_in,
                              void* d_out, int out_size) {
    const int*   data  = (const int*)d_in[0];
    const float* t     = (const float*)d_in[1];
    const float* noise = (const float*)d_in[2];
    float*       out   = (float*)d_out;
    int rows = in_sizes[1];                 // B*S = 16384

    int warps  = (rows + 1) / 2;            // 2 rows per warp
    int blocks = (warps + 7) / 8;           // 8 warps per block
    dbf_kernel<<<blocks, 256>>>(data, t, noise, out, rows);
}